// round 15
// baseline (speedup 1.0000x reference)
#include <cuda_runtime.h>
#include <cuda_fp16.h>
#include <cstdint>
#include <cstddef>

// pre-converted fp16 weights, transposed to [n][k]
__device__ __align__(16) __half g_W1h[128 * 256];
__device__ __align__(16) __half g_W2h[64 * 128];

namespace {

constexpr int THREADS = 512;   // 16 warps: 4 M-warps (32 rows) x 4 N-warps (32 cols)
constexpr int BPB     = 8;
constexpr int ROWS    = 112;   // real rows; M padded to 128
constexpr int MPAD    = 128;

constexpr int XSW  = 20;   // X fp16 chunk stride (words)
constexpr int WSW  = 20;   // W1 fp16 chunk stride
constexpr int HSW  = 68;   // Y/H fp16 stride (words)
constexpr int W2SW = 68;   // W2T fp16 stride
constexpr int ZSF  = 72;   // Z f32 stride (floats)

constexpr int XBUFW = MPAD * XSW;   // 2560 words per X buffer
constexpr int WBUFW = 128 * WSW;    // 2560 words per W1 buffer

// byte offsets; union region holds {X+W1 staging | YH fp16 | Z f32}
constexpr int O_BIAS = 0;                       // b1(512B)+b2(256B)
constexpr int O_X    = 1024;                    // 2*2560*4 = 20480
constexpr int O_W1   = O_X + 2 * XBUFW * 4;     // 21504: 2*2560*4 = 20480
constexpr int UNION  = 40960;                   // staging 40960 | YH 34816 | Z 36864
constexpr int O_W2   = O_X + UNION;             // 41984
constexpr int SMEM_BYTES = O_W2 + 64 * W2SW * 4;  // 59392

__device__ __forceinline__ uint32_t packh2(float a, float b) {
    __half2 h = __floats2half2_rn(a, b);
    return *reinterpret_cast<uint32_t*>(&h);
}

__device__ __forceinline__ void mma16816(float* d,
                                         uint32_t a0, uint32_t a1, uint32_t a2, uint32_t a3,
                                         uint32_t b0, uint32_t b1) {
    asm volatile(
        "mma.sync.aligned.m16n8k16.row.col.f32.f16.f16.f32 "
        "{%0,%1,%2,%3},{%4,%5,%6,%7},{%8,%9},{%0,%1,%2,%3};\n"
        : "+f"(d[0]), "+f"(d[1]), "+f"(d[2]), "+f"(d[3])
        : "r"(a0), "r"(a1), "r"(a2), "r"(a3), "r"(b0), "r"(b1));
}

__device__ __forceinline__ void cp16(uint32_t dst_smem, const void* src) {
    asm volatile("cp.async.cg.shared.global [%0], [%1], 16;\n"
                 :: "r"(dst_smem), "l"(src));
}
__device__ __forceinline__ void cp_commit() {
    asm volatile("cp.async.commit_group;\n" ::: "memory");
}
__device__ __forceinline__ void cp_wait0() {
    asm volatile("cp.async.wait_group 0;\n" ::: "memory");
}

// A_hat: degrees (with self-loop) = 3 at teeth {0,6,7,13}, else 4
constexpr float CA = 0.3333333333333333f;
constexpr float CB = 0.28867513459481287f;
constexpr float CC = 0.25f;

__device__ __forceinline__ float2 m3(float wa, float2 a, float wb, float2 b,
                                     float wc, float2 c) {
    return make_float2(wa * a.x + wb * b.x + wc * c.x,
                       wa * a.y + wb * b.y + wc * c.y);
}
__device__ __forceinline__ float2 m4(float wa, float2 a, float wb, float2 b,
                                     float wc, float2 c, float wd, float2 d) {
    return make_float2(wa * a.x + wb * b.x + wc * c.x + wd * d.x,
                       wa * a.y + wb * b.y + wc * c.y + wd * d.y);
}

__device__ __forceinline__ void ahat14(const float* y, float* o) {
    o[0]  = CA*y[0] + CB*y[1] + CA*y[7];
    o[1]  = CB*y[0] + CC*y[1] + CC*y[2]  + CC*y[8];
    o[2]  = CC*y[1] + CC*y[2] + CC*y[3]  + CC*y[9];
    o[3]  = CC*y[2] + CC*y[3] + CC*y[4]  + CC*y[10];
    o[4]  = CC*y[3] + CC*y[4] + CC*y[5]  + CC*y[11];
    o[5]  = CC*y[4] + CC*y[5] + CB*y[6]  + CC*y[12];
    o[6]  = CB*y[5] + CA*y[6] + CA*y[13];
    o[7]  = CA*y[0] + CA*y[7] + CB*y[8];
    o[8]  = CC*y[1] + CB*y[7] + CC*y[8]  + CC*y[9];
    o[9]  = CC*y[2] + CC*y[8] + CC*y[9]  + CC*y[10];
    o[10] = CC*y[3] + CC*y[9] + CC*y[10] + CC*y[11];
    o[11] = CC*y[4] + CC*y[10]+ CC*y[11] + CC*y[12];
    o[12] = CC*y[5] + CC*y[11]+ CC*y[12] + CB*y[13];
    o[13] = CA*y[6] + CB*y[12]+ CA*y[13];
}

} // namespace

__global__ void prep_kernel(const float* __restrict__ W1, const float* __restrict__ W2) {
    int t = blockIdx.x * 256 + threadIdx.x;
    if (t < 32768) {
        int n = t >> 8, k = t & 255;
        g_W1h[n * 256 + k] = __float2half_rn(W1[k * 128 + n]);
    } else if (t < 40960) {
        int u = t - 32768;
        int n = u >> 7, k = u & 127;
        g_W2h[n * 128 + k] = __float2half_rn(W2[k * 64 + n]);
    }
}

__global__ void __launch_bounds__(THREADS, 2)
gcn_t32_kernel(const float* __restrict__ fea,
               const float* __restrict__ b1,
               const float* __restrict__ b2,
               float* __restrict__ out)
{
    extern __shared__ char sm[];
    const uint32_t smb = (uint32_t)__cvta_generic_to_shared(sm);

    float*    b1s = (float*)(sm + O_BIAS);
    float*    b2s = (float*)(sm + O_BIAS + 512);
    uint32_t* Xw  = (uint32_t*)(sm + O_X);
    uint32_t* W1w = (uint32_t*)(sm + O_W1);
    uint32_t* YHw = (uint32_t*)(sm + O_X);     // [128][68w] fp16, aliases staging
    float*    Zf  = (float*)(sm + O_X);        // [128][72]  f32,  aliases staging
    uint32_t* W2w = (uint32_t*)(sm + O_W2);

    const int tid  = threadIdx.x;
    const int warp = tid >> 5;
    const int lane = tid & 31;
    const int g    = lane >> 2;
    const int t    = lane & 3;
    const int wm   = warp >> 2;   // 0..3: 32-row M tile
    const int wn   = warp & 3;    // 0..3: 32-col N tile
    const int blk  = blockIdx.x;

    const float* feaB = fea + (size_t)blk * ROWS * 256;

    // X staging map: 448 uint4 per chunk (112 rows x 4 segs), 1 per thread (tid<448)
    const int xrow = tid >> 2, xseg = tid & 3;
    const bool hasx = tid < 448;

    // ---------------- prologue ----------------
    if (tid < 128) b1s[tid] = b1[tid];
    else if (tid < 192) b2s[tid - 128] = b2[tid - 128];

    // zero pad rows 112..127 of BOTH X buffers
    for (int i = tid; i < 2 * 16 * XSW; i += THREADS) {
        int buf = i / (16 * XSW), r = (i / XSW) % 16, w = i % XSW;
        Xw[buf * XBUFW + (112 + r) * XSW + w] = 0u;
    }

    // W2T (1024 x 16B, 2 per thread)
    #pragma unroll
    for (int j = 0; j < 2; ++j) {
        int i = tid + j * THREADS;
        int n = i >> 4, seg = i & 15;
        cp16(smb + O_W2 + (uint32_t)(n * W2SW + seg * 4) * 4,
             g_W2h + n * 128 + seg * 8);
    }
    // W1 chunk 0 (512 x 16B, exactly 1 per thread)
    {
        int n = tid >> 2, seg = tid & 3;
        cp16(smb + O_W1 + (uint32_t)(n * WSW + seg * 4) * 4,
             g_W1h + n * 256 + seg * 8);
    }
    cp_commit();

    // X chunk 0 (pack-early, store to buf0)
    if (hasx) {
        const float* xp = feaB + xrow * 256 + xseg * 8;
        float4 v0 = *(const float4*)xp;
        float4 v1 = *(const float4*)(xp + 4);
        *(uint4*)(Xw + xrow * XSW + xseg * 4) =
            make_uint4(packh2(v0.x, v0.y), packh2(v0.z, v0.w),
                       packh2(v1.x, v1.y), packh2(v1.z, v1.w));
    }
    cp_wait0();
    __syncthreads();

    // ---------------- GEMM1: Y[128,128] = Xpad * W1T^T, K=256 ----------------
    float acc1[2][4][4];
    #pragma unroll
    for (int mt = 0; mt < 2; ++mt)
        #pragma unroll
        for (int nt = 0; nt < 4; ++nt)
            #pragma unroll
            for (int r = 0; r < 4; ++r) acc1[mt][nt][r] = 0.f;

    #pragma unroll 1
    for (int c = 0; c < 8; ++c) {
        uint4 xu;
        if (c < 7) {
            int k0 = (c + 1) * 32;
            if (hasx) {
                const float* xp = feaB + xrow * 256 + k0 + xseg * 8;
                float4 v0 = *(const float4*)xp;
                float4 v1 = *(const float4*)(xp + 4);
                xu = make_uint4(packh2(v0.x, v0.y), packh2(v0.z, v0.w),
                                packh2(v1.x, v1.y), packh2(v1.z, v1.w));
            }
            uint32_t wdst = smb + O_W1 + (uint32_t)(((c + 1) & 1) * WBUFW) * 4;
            {
                int n = tid >> 2, seg = tid & 3;
                cp16(wdst + (uint32_t)(n * WSW + seg * 4) * 4,
                     g_W1h + n * 256 + k0 + seg * 8);
            }
            cp_commit();
        }

        const uint32_t* xb = Xw + (c & 1) * XBUFW;
        const uint32_t* wb = W1w + (c & 1) * WBUFW;
        #pragma unroll
        for (int s = 0; s < 2; ++s) {
            uint32_t a[2][4];
            #pragma unroll
            for (int mt = 0; mt < 2; ++mt) {
                const uint32_t* ap = xb + (wm * 32 + mt * 16 + g) * XSW + s * 8 + t;
                a[mt][0] = ap[0];
                a[mt][1] = ap[8 * XSW];
                a[mt][2] = ap[4];
                a[mt][3] = ap[8 * XSW + 4];
            }
            const uint32_t* bp0 = wb + (wn * 32 + g) * WSW + s * 8 + t;
            #pragma unroll
            for (int nt = 0; nt < 4; ++nt) {
                const uint32_t* bp = bp0 + nt * 8 * WSW;
                uint32_t b0 = bp[0], b1v = bp[4];
                mma16816(acc1[0][nt], a[0][0], a[0][1], a[0][2], a[0][3], b0, b1v);
                mma16816(acc1[1][nt], a[1][0], a[1][1], a[1][2], a[1][3], b0, b1v);
            }
        }

        if (c < 7) {
            if (hasx) {
                uint32_t* xw = Xw + ((c + 1) & 1) * XBUFW;
                *(uint4*)(xw + xrow * XSW + xseg * 4) = xu;
            }
            cp_wait0();
        }
        __syncthreads();
    }

    // ---------------- Y -> YH (fp16, aliases staging; GEMM1 done+synced) ----------------
    #pragma unroll
    for (int mt = 0; mt < 2; ++mt) {
        int r0 = wm * 32 + mt * 16 + g;
        __half2* h0 = (__half2*)YHw + r0 * HSW + wn * 16 + t;
        __half2* h1 = h0 + 8 * HSW;
        #pragma unroll
        for (int nt = 0; nt < 4; ++nt) {
            h0[nt * 4] = __floats2half2_rn(acc1[mt][nt][0], acc1[mt][nt][1]);
            h1[nt * 4] = __floats2half2_rn(acc1[mt][nt][2], acc1[mt][nt][3]);
        }
    }
    __syncthreads();

    // ---------------- A_hat pass 1 (+b1, relu), in place on fp16 YH ----------------
    {
        const float2* b1s2 = (const float2*)b1s;
        int b = tid >> 6, cw = tid & 63;                 // 512 tasks, 1/thread
        __half2* p = (__half2*)YHw + (b * 14) * HSW + cw;
        float2 y[14];
        #pragma unroll
        for (int i = 0; i < 14; ++i) y[i] = __half22float2(p[i * HSW]);
        float2 bias = b1s2[cw];
        float2 o[14];
        o[0]  = m3(CA,y[0], CB,y[1], CA,y[7]);
        o[1]  = m4(CB,y[0], CC,y[1], CC,y[2],  CC,y[8]);
        o[2]  = m4(CC,y[1], CC,y[2], CC,y[3],  CC,y[9]);
        o[3]  = m4(CC,y[2], CC,y[3], CC,y[4],  CC,y[10]);
        o[4]  = m4(CC,y[3], CC,y[4], CC,y[5],  CC,y[11]);
        o[5]  = m4(CC,y[4], CC,y[5], CB,y[6],  CC,y[12]);
        o[6]  = m3(CB,y[5], CA,y[6], CA,y[13]);
        o[7]  = m3(CA,y[0], CA,y[7], CB,y[8]);
        o[8]  = m4(CC,y[1], CB,y[7], CC,y[8],  CC,y[9]);
        o[9]  = m4(CC,y[2], CC,y[8], CC,y[9],  CC,y[10]);
        o[10] = m4(CC,y[3], CC,y[9], CC,y[10], CC,y[11]);
        o[11] = m4(CC,y[4], CC,y[10],CC,y[11], CC,y[12]);
        o[12] = m4(CC,y[5], CC,y[11],CC,y[12], CB,y[13]);
        o[13] = m3(CA,y[6], CB,y[12],CA,y[13]);
        #pragma unroll
        for (int i = 0; i < 14; ++i) {
            p[i * HSW] = __floats2half2_rn(fmaxf(o[i].x + bias.x, 0.f),
                                           fmaxf(o[i].y + bias.y, 0.f));
        }
    }
    __syncthreads();

    // ---------------- GEMM2: Z[128,64] = H * W2T^T, K=128 ----------------
    float acc2[2][2][4];
    #pragma unroll
    for (int mt = 0; mt < 2; ++mt)
        #pragma unroll
        for (int nt = 0; nt < 2; ++nt)
            #pragma unroll
            for (int r = 0; r < 4; ++r) acc2[mt][nt][r] = 0.f;

    #pragma unroll
    for (int s = 0; s < 8; ++s) {
        uint32_t a[2][4];
        #pragma unroll
        for (int mt = 0; mt < 2; ++mt) {
            const uint32_t* ap = YHw + (wm * 32 + mt * 16 + g) * HSW + s * 8 + t;
            a[mt][0] = ap[0];
            a[mt][1] = ap[8 * HSW];
            a[mt][2] = ap[4];
            a[mt][3] = ap[8 * HSW + 4];
        }
        const uint32_t* bp0 = W2w + (wn * 16 + g) * W2SW + s * 8 + t;
        #pragma unroll
        for (int nt = 0; nt < 2; ++nt) {
            const uint32_t* bp = bp0 + nt * 8 * W2SW;
            uint32_t b0 = bp[0], b1v = bp[4];
            mma16816(acc2[0][nt], a[0][0], a[0][1], a[0][2], a[0][3], b0, b1v);
            mma16816(acc2[1][nt], a[1][0], a[1][1], a[1][2], a[1][3], b0, b1v);
        }
    }
    __syncthreads();   // all YH reads done before Z overwrites the region

    // ---------------- Z -> smem (f32) ----------------
    #pragma unroll
    for (int mt = 0; mt < 2; ++mt) {
        int r0 = wm * 32 + mt * 16 + g;
        float* z0 = Zf + r0 * ZSF + wn * 16 + 2 * t;
        float* z1 = z0 + 8 * ZSF;
        #pragma unroll
        for (int nt = 0; nt < 2; ++nt) {
            *(float2*)(z0 + nt * 8) = make_float2(acc2[mt][nt][0], acc2[mt][nt][1]);
            *(float2*)(z1 + nt * 8) = make_float2(acc2[mt][nt][2], acc2[mt][nt][3]);
        }
    }
    __syncthreads();

    // ---------------- A_hat pass 2 (+b2) -> global ----------------
    {
        float* gout = out + (size_t)blk * ROWS * 64;
        int b = tid >> 6, col = tid & 63;                // 512 tasks, 1/thread
        const float* zp = Zf + b * 14 * ZSF + col;
        float z[14], o[14];
        #pragma unroll
        for (int i = 0; i < 14; ++i) z[i] = zp[i * ZSF];
        ahat14(z, o);
        float bv = b2s[col];
        float* gp = gout + (b * 14) * 64 + col;
        #pragma unroll
        for (int i = 0; i < 14; ++i) gp[i * 64] = o[i] + bv;
    }
}

extern "C" void kernel_launch(void* const* d_in, const int* in_sizes, int n_in,
                              void* d_out, int out_size) {
    const float* fea = (const float*)d_in[0];
    const float* W1  = (const float*)d_in[1];
    const float* b1  = (const float*)d_in[2];
    const float* W2  = (const float*)d_in[3];
    const float* b2  = (const float*)d_in[4];
    float* out = (float*)d_out;

    int B = in_sizes[0] / (14 * 256);   // 16384
    int blocks = B / BPB;               // 2048

    prep_kernel<<<160, 256>>>(W1, W2);
    cudaFuncSetAttribute(gcn_t32_kernel,
                         cudaFuncAttributeMaxDynamicSharedMemorySize, SMEM_BYTES);
    gcn_t32_kernel<<<blocks, THREADS, SMEM_BYTES>>>(fea, b1, b2, out);
}

// round 16
// speedup vs baseline: 1.2219x; 1.2219x over previous
#include <cuda_runtime.h>
#include <cuda_fp16.h>
#include <cstdint>
#include <cstddef>

// pre-converted fp16 weights, transposed to [n][k]
__device__ __align__(16) __half g_W1h[128 * 256];
__device__ __align__(16) __half g_W2h[64 * 128];

namespace {

constexpr int THREADS = 448;   // 14 warps: 7 M-warps (32 rows) x 2 N-warps (64 cols)
constexpr int BPB     = 16;
constexpr int ROWS    = 224;

constexpr int XSW  = 20;   // X fp16 chunk stride (words)
constexpr int W1SW = 132;  // W1T full-K stride (words): 128 data + 4 pad (132%32==4)
constexpr int HSW  = 68;   // Y/H fp16 stride (words)
constexpr int W2SW = 68;   // W2T fp16 stride (words)
constexpr int ZSW  = 36;   // Z half2 stride (words): 32 data + 4 pad

constexpr int XBUFW = ROWS * XSW;   // 4480 words per X buffer

// byte offsets
constexpr int O_BIAS = 0;                       // b1(512B)+b2(256B)
constexpr int O_W1   = 1024;                    // 128*132*4 = 67584 (FULL W1, resident)
constexpr int O_W2   = O_W1 + 128 * W1SW * 4;   // 68608: 64*68*4 = 17408
constexpr int O_UNI  = O_W2 + 64 * W2SW * 4;    // 86016
// union at O_UNI: X 2 bufs (35840) | YH fp16 (60928) | Z half2 (32256)
constexpr int SMEM_BYTES = O_UNI + ROWS * HSW * 4;  // 146944

__device__ __forceinline__ uint32_t packh2(float a, float b) {
    __half2 h = __floats2half2_rn(a, b);
    return *reinterpret_cast<uint32_t*>(&h);
}

__device__ __forceinline__ void mma16816(float* d,
                                         uint32_t a0, uint32_t a1, uint32_t a2, uint32_t a3,
                                         uint32_t b0, uint32_t b1) {
    asm volatile(
        "mma.sync.aligned.m16n8k16.row.col.f32.f16.f16.f32 "
        "{%0,%1,%2,%3},{%4,%5,%6,%7},{%8,%9},{%0,%1,%2,%3};\n"
        : "+f"(d[0]), "+f"(d[1]), "+f"(d[2]), "+f"(d[3])
        : "r"(a0), "r"(a1), "r"(a2), "r"(a3), "r"(b0), "r"(b1));
}

__device__ __forceinline__ void cp16(uint32_t dst_smem, const void* src) {
    asm volatile("cp.async.cg.shared.global [%0], [%1], 16;\n"
                 :: "r"(dst_smem), "l"(src));
}
__device__ __forceinline__ void cp_commit() {
    asm volatile("cp.async.commit_group;\n" ::: "memory");
}
__device__ __forceinline__ void cp_wait0() {
    asm volatile("cp.async.wait_group 0;\n" ::: "memory");
}

// A_hat: degrees (with self-loop) = 3 at teeth {0,6,7,13}, else 4
constexpr float CA = 0.3333333333333333f;
constexpr float CB = 0.28867513459481287f;
constexpr float CC = 0.25f;

__device__ __forceinline__ float2 m3(float wa, float2 a, float wb, float2 b,
                                     float wc, float2 c) {
    return make_float2(wa * a.x + wb * b.x + wc * c.x,
                       wa * a.y + wb * b.y + wc * c.y);
}
__device__ __forceinline__ float2 m4(float wa, float2 a, float wb, float2 b,
                                     float wc, float2 c, float wd, float2 d) {
    return make_float2(wa * a.x + wb * b.x + wc * c.x + wd * d.x,
                       wa * a.y + wb * b.y + wc * c.y + wd * d.y);
}

__device__ __forceinline__ void ahat2_cols(const float2* y, float2* o) {
    o[0]  = m3(CA,y[0], CB,y[1], CA,y[7]);
    o[1]  = m4(CB,y[0], CC,y[1], CC,y[2],  CC,y[8]);
    o[2]  = m4(CC,y[1], CC,y[2], CC,y[3],  CC,y[9]);
    o[3]  = m4(CC,y[2], CC,y[3], CC,y[4],  CC,y[10]);
    o[4]  = m4(CC,y[3], CC,y[4], CC,y[5],  CC,y[11]);
    o[5]  = m4(CC,y[4], CC,y[5], CB,y[6],  CC,y[12]);
    o[6]  = m3(CB,y[5], CA,y[6], CA,y[13]);
    o[7]  = m3(CA,y[0], CA,y[7], CB,y[8]);
    o[8]  = m4(CC,y[1], CB,y[7], CC,y[8],  CC,y[9]);
    o[9]  = m4(CC,y[2], CC,y[8], CC,y[9],  CC,y[10]);
    o[10] = m4(CC,y[3], CC,y[9], CC,y[10], CC,y[11]);
    o[11] = m4(CC,y[4], CC,y[10],CC,y[11], CC,y[12]);
    o[12] = m4(CC,y[5], CC,y[11],CC,y[12], CB,y[13]);
    o[13] = m3(CA,y[6], CB,y[12],CA,y[13]);
}

} // namespace

__global__ void prep_kernel(const float* __restrict__ W1, const float* __restrict__ W2) {
    int t = blockIdx.x * 256 + threadIdx.x;
    if (t < 32768) {
        int n = t >> 8, k = t & 255;
        g_W1h[n * 256 + k] = __float2half_rn(W1[k * 128 + n]);
    } else if (t < 40960) {
        int u = t - 32768;
        int n = u >> 7, k = u & 127;
        g_W2h[n * 128 + k] = __float2half_rn(W2[k * 64 + n]);
    }
}

__global__ void __launch_bounds__(THREADS, 1)
gcn_resw_kernel(const float* __restrict__ fea,
                const float* __restrict__ b1,
                const float* __restrict__ b2,
                float* __restrict__ out)
{
    extern __shared__ char sm[];
    const uint32_t smb = (uint32_t)__cvta_generic_to_shared(sm);

    float*    b1s = (float*)(sm + O_BIAS);
    float*    b2s = (float*)(sm + O_BIAS + 512);
    uint32_t* W1w = (uint32_t*)(sm + O_W1);
    uint32_t* W2w = (uint32_t*)(sm + O_W2);
    uint32_t* Xw  = (uint32_t*)(sm + O_UNI);   // 2 staging buffers
    uint32_t* YHw = (uint32_t*)(sm + O_UNI);   // [224][68w] fp16, aliases X
    __half2*  Zh  = (__half2*)(sm + O_UNI);    // [224][36w] half2, aliases YH

    const int tid  = threadIdx.x;
    const int warp = tid >> 5;
    const int lane = tid & 31;
    const int g    = lane >> 2;
    const int t    = lane & 3;
    const int wm   = warp >> 1;   // 0..6: 32-row M tile
    const int wn   = warp & 1;    // 0..1: 64-col N tile
    const int blk  = blockIdx.x;

    const float* feaB = fea + (size_t)blk * ROWS * 256;

    // X staging map: 896 uint4 per chunk = exactly 2 per thread
    const int xrow0 = tid >> 2,         xseg0 = tid & 3;
    const int xrow1 = (tid + 448) >> 2, xseg1 = (tid + 448) & 3;

    // ---------------- prologue ----------------
    if (tid < 128) b1s[tid] = b1[tid];
    else if (tid < 192) b2s[tid - 128] = b2[tid - 128];

    // FULL W1T resident: 128 rows x 256 halves = 4096 x 16B
    for (int i = tid; i < 4096; i += THREADS) {
        int n = i >> 5, q = i & 31;
        cp16(smb + O_W1 + (uint32_t)(n * W1SW + q * 4) * 4,
             g_W1h + n * 256 + q * 8);
    }
    // W2T: 1024 x 16B
    for (int i = tid; i < 1024; i += THREADS) {
        int n = i >> 4, q = i & 15;
        cp16(smb + O_W2 + (uint32_t)(n * W2SW + q * 4) * 4,
             g_W2h + n * 128 + q * 8);
    }
    cp_commit();

    // X chunk 0 -> buf0 (load+pack+store)
    float4 xf[4];
    {
        const float* xp = feaB + xrow0 * 256 + xseg0 * 8;
        const float* xq = feaB + xrow1 * 256 + xseg1 * 8;
        float4 a0 = *(const float4*)xp, a1 = *(const float4*)(xp + 4);
        float4 c0 = *(const float4*)xq, c1 = *(const float4*)(xq + 4);
        *(uint4*)(Xw + xrow0 * XSW + xseg0 * 4) =
            make_uint4(packh2(a0.x, a0.y), packh2(a0.z, a0.w),
                       packh2(a1.x, a1.y), packh2(a1.z, a1.w));
        *(uint4*)(Xw + xrow1 * XSW + xseg1 * 4) =
            make_uint4(packh2(c0.x, c0.y), packh2(c0.z, c0.w),
                       packh2(c1.x, c1.y), packh2(c1.z, c1.w));
    }
    // X chunk 1 -> regs (packed+stored at top of iter 0)
    {
        const float* xp = feaB + xrow0 * 256 + 32 + xseg0 * 8;
        const float* xq = feaB + xrow1 * 256 + 32 + xseg1 * 8;
        xf[0] = *(const float4*)xp; xf[1] = *(const float4*)(xp + 4);
        xf[2] = *(const float4*)xq; xf[3] = *(const float4*)(xq + 4);
    }
    cp_wait0();
    __syncthreads();

    // ---------------- GEMM1: Y[224,128] = X * W1T^T, K=256, W1 resident ----------------
    float acc1[2][8][4];
    #pragma unroll
    for (int mt = 0; mt < 2; ++mt)
        #pragma unroll
        for (int nt = 0; nt < 8; ++nt)
            #pragma unroll
            for (int r = 0; r < 4; ++r) acc1[mt][nt][r] = 0.f;

    #pragma unroll 1
    for (int c = 0; c < 8; ++c) {
        // 1. pack + store chunk c+1 (floats loaded one iteration ago)
        if (c + 1 < 8) {
            uint32_t* xw = Xw + ((c + 1) & 1) * XBUFW;
            *(uint4*)(xw + xrow0 * XSW + xseg0 * 4) =
                make_uint4(packh2(xf[0].x, xf[0].y), packh2(xf[0].z, xf[0].w),
                           packh2(xf[1].x, xf[1].y), packh2(xf[1].z, xf[1].w));
            *(uint4*)(xw + xrow1 * XSW + xseg1 * 4) =
                make_uint4(packh2(xf[2].x, xf[2].y), packh2(xf[2].z, xf[2].w),
                           packh2(xf[3].x, xf[3].y), packh2(xf[3].z, xf[3].w));
        }
        // 2. issue LDG for chunk c+2
        if (c + 2 < 8) {
            int k0 = (c + 2) * 32;
            const float* xp = feaB + xrow0 * 256 + k0 + xseg0 * 8;
            const float* xq = feaB + xrow1 * 256 + k0 + xseg1 * 8;
            xf[0] = *(const float4*)xp; xf[1] = *(const float4*)(xp + 4);
            xf[2] = *(const float4*)xq; xf[3] = *(const float4*)(xq + 4);
        }

        // 3. mma on chunk c (B from resident W1)
        const uint32_t* xb = Xw + (c & 1) * XBUFW;
        #pragma unroll
        for (int s = 0; s < 2; ++s) {
            uint32_t a[2][4];
            #pragma unroll
            for (int mt = 0; mt < 2; ++mt) {
                const uint32_t* ap = xb + (wm * 32 + mt * 16 + g) * XSW + s * 8 + t;
                a[mt][0] = ap[0];
                a[mt][1] = ap[8 * XSW];
                a[mt][2] = ap[4];
                a[mt][3] = ap[8 * XSW + 4];
            }
            const uint32_t* bp0 = W1w + (wn * 64 + g) * W1SW + c * 16 + s * 8 + t;
            #pragma unroll
            for (int nt = 0; nt < 8; ++nt) {
                const uint32_t* bp = bp0 + nt * 8 * W1SW;
                uint32_t b0 = bp[0], b1v = bp[4];
                mma16816(acc1[0][nt], a[0][0], a[0][1], a[0][2], a[0][3], b0, b1v);
                mma16816(acc1[1][nt], a[1][0], a[1][1], a[1][2], a[1][3], b0, b1v);
            }
        }
        __syncthreads();
    }

    // ---------------- Y -> YH (fp16, aliases X staging; GEMM1 done+synced) ----------------
    #pragma unroll
    for (int mt = 0; mt < 2; ++mt) {
        int r0 = wm * 32 + mt * 16 + g;
        __half2* h0 = (__half2*)YHw + r0 * HSW + wn * 32 + t;
        __half2* h1 = h0 + 8 * HSW;
        #pragma unroll
        for (int nt = 0; nt < 8; ++nt) {
            h0[nt * 4] = __floats2half2_rn(acc1[mt][nt][0], acc1[mt][nt][1]);
            h1[nt * 4] = __floats2half2_rn(acc1[mt][nt][2], acc1[mt][nt][3]);
        }
    }
    __syncthreads();

    // ---------------- A_hat pass 1 (+b1, relu), in place on fp16 YH ----------------
    const float2* b1s2 = (const float2*)b1s;
    for (int task = tid; task < BPB * 64; task += THREADS) {
        int b = task >> 6, cw = task & 63;
        __half2* p = (__half2*)YHw + (b * 14) * HSW + cw;
        float2 y[14], o[14];
        #pragma unroll
        for (int i = 0; i < 14; ++i) y[i] = __half22float2(p[i * HSW]);
        ahat2_cols(y, o);
        float2 bias = b1s2[cw];
        #pragma unroll
        for (int i = 0; i < 14; ++i) {
            p[i * HSW] = __floats2half2_rn(fmaxf(o[i].x + bias.x, 0.f),
                                           fmaxf(o[i].y + bias.y, 0.f));
        }
    }
    __syncthreads();

    // ---------------- GEMM2: Z[224,64] = H * W2T^T, K=128 ----------------
    float acc2[2][4][4];
    #pragma unroll
    for (int mt = 0; mt < 2; ++mt)
        #pragma unroll
        for (int nt = 0; nt < 4; ++nt)
            #pragma unroll
            for (int r = 0; r < 4; ++r) acc2[mt][nt][r] = 0.f;

    #pragma unroll
    for (int s = 0; s < 8; ++s) {
        uint32_t a[2][4];
        #pragma unroll
        for (int mt = 0; mt < 2; ++mt) {
            const uint32_t* ap = YHw + (wm * 32 + mt * 16 + g) * HSW + s * 8 + t;
            a[mt][0] = ap[0];
            a[mt][1] = ap[8 * HSW];
            a[mt][2] = ap[4];
            a[mt][3] = ap[8 * HSW + 4];
        }
        const uint32_t* bp0 = W2w + (wn * 32 + g) * W2SW + s * 8 + t;
        #pragma unroll
        for (int nt = 0; nt < 4; ++nt) {
            const uint32_t* bp = bp0 + nt * 8 * W2SW;
            uint32_t b0 = bp[0], b1v = bp[4];
            mma16816(acc2[0][nt], a[0][0], a[0][1], a[0][2], a[0][3], b0, b1v);
            mma16816(acc2[1][nt], a[1][0], a[1][1], a[1][2], a[1][3], b0, b1v);
        }
    }
    __syncthreads();   // all YH reads done before Z (alias) is written

    // ---------------- Z -> smem (fp16) ----------------
    #pragma unroll
    for (int mt = 0; mt < 2; ++mt) {
        int r0 = wm * 32 + mt * 16 + g;
        __half2* z0 = Zh + r0 * ZSW + wn * 16 + t;
        __half2* z1 = z0 + 8 * ZSW;
        #pragma unroll
        for (int nt = 0; nt < 4; ++nt) {
            z0[nt * 4] = __floats2half2_rn(acc2[mt][nt][0], acc2[mt][nt][1]);
            z1[nt * 4] = __floats2half2_rn(acc2[mt][nt][2], acc2[mt][nt][3]);
        }
    }
    __syncthreads();

    // ---------------- A_hat pass 2 (+b2) -> global ----------------
    float* gout = out + (size_t)blk * ROWS * 64;
    const float2* b2s2 = (const float2*)b2s;
    for (int task = tid; task < BPB * 32; task += THREADS) {
        int b = task >> 5, c2 = task & 31;
        const __half2* zp = Zh + (b * 14) * ZSW + c2;
        float2 z[14], o[14];
        #pragma unroll
        for (int i = 0; i < 14; ++i) z[i] = __half22float2(zp[i * ZSW]);
        ahat2_cols(z, o);
        float2 bias = b2s2[c2];
        float* gp = gout + (b * 14) * 64 + 2 * c2;
        #pragma unroll
        for (int i = 0; i < 14; ++i)
            *(float2*)(gp + i * 64) = make_float2(o[i].x + bias.x, o[i].y + bias.y);
    }
}

extern "C" void kernel_launch(void* const* d_in, const int* in_sizes, int n_in,
                              void* d_out, int out_size) {
    const float* fea = (const float*)d_in[0];
    const float* W1  = (const float*)d_in[1];
    const float* b1  = (const float*)d_in[2];
    const float* W2  = (const float*)d_in[3];
    const float* b2  = (const float*)d_in[4];
    float* out = (float*)d_out;

    int B = in_sizes[0] / (14 * 256);   // 16384
    int blocks = B / BPB;               // 1024

    prep_kernel<<<160, 256>>>(W1, W2);
    cudaFuncSetAttribute(gcn_resw_kernel,
                         cudaFuncAttributeMaxDynamicSharedMemorySize, SMEM_BYTES);
    gcn_resw_kernel<<<blocks, THREADS, SMEM_BYTES>>>(fea, b1, b2, out);
}